// round 11
// baseline (speedup 1.0000x reference)
#include <cuda_runtime.h>
#include <cuda_fp16.h>

// Problem constants (BETA = ALPHA = WEIGHT = 1 are compile-time constants in the reference)
#define N_POINTS 4096
#define N_EVENTS 1000000

#define THREADS      256
#define GRID         444                 // 3 CTA/SM floor on 148 SMs -> always <= 1 wave
#define ROWPAIRS     2048                // folded rows: rp -> rows {rp, 4094-rp}
#define PAIR_UNITS   (ROWPAIRS * 4)     // 8192 quarter-row units, 1024 pairs each
#define NVEC         (N_EVENTS / 4)      // 250000 vec4 event packets

__device__ float        g_partials[GRID];
__device__ unsigned int g_count;   // zero-init; last block resets it -> graph-replay safe

__device__ __forceinline__ float block_reduce_sum(float v) {
    __shared__ float sdata[THREADS / 32];
    #pragma unroll
    for (int o = 16; o > 0; o >>= 1) v += __shfl_down_sync(0xffffffffu, v, o);
    const int lane = threadIdx.x & 31;
    const int wid  = threadIdx.x >> 5;
    if (lane == 0) sdata[wid] = v;
    __syncthreads();
    if (wid == 0) {
        v = (lane < THREADS / 32) ? sdata[lane] : 0.0f;
        #pragma unroll
        for (int o = (THREADS / 64); o > 0; o >>= 1) v += __shfl_down_sync(0xffffffffu, v, o);
    }
    return v;
}

__global__ __launch_bounds__(THREADS, 3)
void smallnet_fused_kernel(const float2* __restrict__ z0,
                           const float2* __restrict__ v0,
                           const float*  __restrict__ event_times,
                           const float*  __restrict__ t0p,
                           const float*  __restrict__ tnp,
                           const int*    __restrict__ u_idx,
                           const int*    __restrict__ v_idx,
                           float* __restrict__ out) {
    // fp16 node table for event gathers: (z.x,z.y) in .x, (v.x,v.y) in .y  (32 KB)
    __shared__ uint2 tbl[N_POINTS];

    const int b   = blockIdx.x;
    const int tid = threadIdx.x;

    // ---------------- build fp16 table (coalesced, all blocks) ----------------
    for (int p = tid; p < N_POINTS; p += THREADS) {
        const float2 z = __ldg(&z0[p]);
        const float2 v = __ldg(&v0[p]);
        __half2 hz = __floats2half2_rn(z.x, z.y);
        __half2 hv = __floats2half2_rn(v.x, v.y);
        uint2 e;
        e.x = *reinterpret_cast<unsigned int*>(&hz);
        e.y = *reinterpret_cast<unsigned int*>(&hv);
        tbl[p] = e;
    }
    __syncthreads();

    float acc_ev = 0.0f;   // event term
    float acc_pi = 0.0f;   // pair integrand sum (pre-scaled)

    // ---------------- event term: sum_e (1 - ||dz0 + dv0*t||^2) ----------------
    {
        const int4*   u4 = (const int4*)u_idx;
        const int4*   v4 = (const int4*)v_idx;
        const float4* t4 = (const float4*)event_times;

        for (int e = b * THREADS + tid; e < NVEC; e += GRID * THREADS) {
            const int4   u = __ldg(&u4[e]);
            const int4   v = __ldg(&v4[e]);
            const float4 t = __ldg(&t4[e]);

            #pragma unroll
            for (int k = 0; k < 4; ++k) {
                const uint2 eu = tbl[(&u.x)[k]];
                const uint2 ev = tbl[(&v.x)[k]];
                const float tt = (&t.x)[k];

                const __half2 hzu = *reinterpret_cast<const __half2*>(&eu.x);
                const __half2 hvu = *reinterpret_cast<const __half2*>(&eu.y);
                const __half2 hzv = *reinterpret_cast<const __half2*>(&ev.x);
                const __half2 hvv = *reinterpret_cast<const __half2*>(&ev.y);

                const float2 dz = __half22float2(__hsub2(hzu, hzv));
                const float2 dv = __half22float2(__hsub2(hvu, hvv));

                const float dx = fmaf(dv.x, tt, dz.x);
                const float dy = fmaf(dv.y, tt, dz.y);
                acc_ev += 1.0f - fmaf(dx, dx, dy * dy);   // beta = 1
            }
        }
    }

    // ---------------- non-event (pair) term: GL-4 quadrature ----------------
    // I = (dt/2) * sum_k w_k * exp(E - u_k^2), E = 1 - cross^2/mn2,
    // u_k = (x0 + s*dt*c_k)*sqrt(log2 e) in exp2 domain.
    const float t0 = __ldg(t0p);
    const float tn = __ldg(tnp);
    const float dt = tn - t0;

    const float L  = 1.4426950408889634f;   // log2(e)
    const float SL = 1.2011224087864498f;   // sqrt(log2(e))
    const float C0 = 0.06943184420297371f, C1 = 0.33000947820757187f;
    const float C2 = 0.66999052179242810f, C3 = 0.93056815579702620f;
    const float W0 = 0.3478548451374538f,  W1 = 0.6521451548625461f;
    const float dtSL = dt * SL;

    // unit u: rp = u>>2 (folded row pair), q = u&3 (quarter of the 4096-slot space)
    // slot s in [0,4096): if s < 4095-rp -> i=rp, j=s+rp+1 ; else i=4094-rp, j=s
    // rp == 2047 folds onto itself: slots s >= count0 are duplicates -> masked out.
    for (int u = b; u < PAIR_UNITS; u += GRID) {
        const int rp = u >> 2;
        const int q  = u & 3;
        const int r1 = (N_POINTS - 2) - rp;
        const int count0 = (N_POINTS - 1) - rp;
        const bool self_fold = (rp == ROWPAIRS - 1);

        const float2 zi0 = __ldg(&z0[rp]);
        const float2 vi0 = __ldg(&v0[rp]);
        const float2 zi1 = __ldg(&z0[r1]);
        const float2 vi1 = __ldg(&v0[r1]);

        const int s_base = q * 1024 + tid;

        // batched gather of the 4 j-rows (raise MLP before the math)
        float2 zj[4], vj[4];
        bool   sel[4];
        float  w[4];
        #pragma unroll
        for (int k = 0; k < 4; ++k) {
            const int s = s_base + k * 256;
            sel[k] = (s < count0);
            const int j = sel[k] ? (s + rp + 1) : s;
            w[k] = (sel[k] || !self_fold) ? 1.0f : 0.0f;
            zj[k] = __ldg(&z0[j]);
            vj[k] = __ldg(&v0[j]);
        }

        #pragma unroll
        for (int k = 0; k < 4; ++k) {
            const float zix = sel[k] ? zi0.x : zi1.x;
            const float ziy = sel[k] ? zi0.y : zi1.y;
            const float vix = sel[k] ? vi0.x : vi1.x;
            const float viy = sel[k] ? vi0.y : vi1.y;

            const float a  = zix - zj[k].x;
            const float bb = ziy - zj[k].y;
            const float m  = vix - vj[k].x;
            const float n  = viy - vj[k].y;

            const float mn2   = fmaf(m, m, n * n);
            const float inv_s = rsqrtf(mn2);             // alpha = 1
            const float cross = fmaf(a, n, -bb * m);
            const float dot   = fmaf(a, m,  bb * n);

            const float s_   = mn2 * inv_s;
            const float isSL = inv_s * SL;
            const float x0s  = fmaf(mn2, t0, dot) * isSL;   // x0 * sqrt(L)
            const float dS   = s_ * dtSL;                   // (x1-x0) * sqrt(L)

            const float q2   = (cross * cross) * (inv_s * inv_s);
            const float Elog = fmaf(-L, q2, L);             // L*(1 - cross^2/mn2)

            const float u0 = fmaf(C0, dS, x0s);
            const float u1 = fmaf(C1, dS, x0s);
            const float u2 = fmaf(C2, dS, x0s);
            const float u3 = fmaf(C3, dS, x0s);

            const float e0 = exp2f(fmaf(-u0, u0, Elog));
            const float e1 = exp2f(fmaf(-u1, u1, Elog));
            const float e2 = exp2f(fmaf(-u2, u2, Elog));
            const float e3 = exp2f(fmaf(-u3, u3, Elog));

            float g = W0 * e0;
            g = fmaf(W1, e1, g);
            g = fmaf(W1, e2, g);
            g = fmaf(W0, e3, g);
            acc_pi = fmaf(g, w[k], acc_pi);
        }
    }

    // combined partial: event term minus (dt/2)*pair_sum
    const float tot = block_reduce_sum(fmaf(-0.5f * dt, acc_pi, acc_ev));
    float partial = tot;

    // ---- grid-wide deterministic reduction: last block sums all partials ----
    __shared__ bool is_last;
    if (tid == 0) {
        g_partials[b] = partial;
        __threadfence();
        const unsigned int old = atomicAdd(&g_count, 1u);
        is_last = (old == (unsigned int)(GRID - 1));
    }
    __syncthreads();

    if (is_last) {
        __threadfence();
        float s = 0.0f;
        for (int i = tid; i < GRID; i += THREADS) s += g_partials[i];
        s = block_reduce_sum(s);
        if (tid == 0) {
            out[0]  = s;
            g_count = 0;   // reset for next graph replay
        }
    }
}

extern "C" void kernel_launch(void* const* d_in, const int* in_sizes, int n_in,
                              void* d_out, int out_size) {
    // metadata order: z0[4096,2], v0[4096,2], event_times[1e6], t0[], tn[], u_idx[1e6], v_idx[1e6]
    const float2* z0 = (const float2*)d_in[0];
    const float2* v0 = (const float2*)d_in[1];
    const float*  et = (const float*)d_in[2];
    const float*  t0 = (const float*)d_in[3];
    const float*  tn = (const float*)d_in[4];
    const int*    ui = (const int*)d_in[5];
    const int*    vi = (const int*)d_in[6];
    float* out = (float*)d_out;

    smallnet_fused_kernel<<<GRID, THREADS>>>(z0, v0, et, t0, tn, ui, vi, out);
}